// round 1
// baseline (speedup 1.0000x reference)
#include <cuda_runtime.h>
#include <math.h>

#define BB    8
#define CIN   256
#define COUT  256
#define NP    8192
#define KT    9
#define DILT  6
#define PADT  24

// ---------------- device scratch (no allocations allowed) ----------------
__device__ float g_gw[BB * KT * NP];        // gate weights  [b][k][n]
__device__ float g_Wt[KT * CIN * COUT];     // W transposed  [k][c][o]
__device__ float g_sum[COUT];
__device__ float g_sumsq[COUT];
__device__ float g_scale[COUT];
__device__ float g_shift[COUT];

// ---------------- kernel 0: zero the stat accumulators ----------------
__global__ void zero_sums_kernel() {
    int t = threadIdx.x;
    g_sum[t]   = 0.f;
    g_sumsq[t] = 0.f;
}

// ---------------- kernel 1: tap gate weights ----------------
__global__ void gweight_kernel(const float* __restrict__ coords,
                               const float* __restrict__ rot,
                               const float* __restrict__ dist) {
    int n = blockIdx.x * blockDim.x + threadIdx.x;
    int b = blockIdx.y;
    const float* cb = coords + (size_t)b * 3 * NP;
    const float* rb = rot    + (size_t)b * 3 * NP;

    float c0x = cb[n], c0y = cb[NP + n], c0z = cb[2 * NP + n];
    float r0x = rb[n], r0y = rb[NP + n], r0z = rb[2 * NP + n];
    float d0  = dist[(size_t)b * NP + n];
    float r0sq = r0x * r0x + r0y * r0y + r0z * r0z;

#pragma unroll
    for (int k = 0; k < KT; k++) {
        int j = n + k * DILT - PADT;
        float cjx = 0.f, cjy = 0.f, cjz = 0.f;
        float rjx = 0.f, rjy = 0.f, rjz = 0.f;
        float dj  = 0.f;
        if (j >= 0 && j < NP) {
            cjx = cb[j]; cjy = cb[NP + j]; cjz = cb[2 * NP + j];
            rjx = rb[j]; rjy = rb[NP + j]; rjz = rb[2 * NP + j];
            dj  = dist[(size_t)b * NP + j];
        }
        float dx = c0x - cjx, dy = c0y - cjy, dz = c0z - cjz;
        float dc = dx * dx + dy * dy + dz * dz;
        float dd = (d0 - dj) * (d0 - dj);
        float g  = expf(-0.5f * (dc + dd));          // sigma = 1
        float num  = r0x * rjx + r0y * rjy + r0z * rjz;
        float rjsq = rjx * rjx + rjy * rjy + rjz * rjz;
        float den  = sqrtf(r0sq * rjsq) + 1e-8f;
        g_gw[((size_t)b * KT + k) * NP + n] = g * fabsf(num / den);
    }
}

// ---------------- kernel 2: transpose W -> [k][c][o] (coalesced GEMM A loads) ----
__global__ void wtrans_kernel(const float* __restrict__ W) {
    int idx = blockIdx.x * blockDim.x + threadIdx.x;   // idx over Cout*Cin*K
    if (idx >= COUT * CIN * KT) return;
    int k = idx % KT;
    int t = idx / KT;
    int c = t % CIN;
    int o = t / CIN;
    g_Wt[((size_t)k * CIN + c) * COUT + o] = W[idx];
}

// ---------------- kernel 3: fused gated dilated conv (SGEMM-style) ----------------
// Block: 256 threads, computes 128(o) x 128(n) tile for one b.
// K-dim = (k, c) pairs; gate folded into the B tile at staging time.
__global__ __launch_bounds__(256, 2) void conv_kernel(
    const float* __restrict__ x,
    const float* __restrict__ bias,
    float* __restrict__ out) {

    __shared__ float As[8][128];
    __shared__ float Bs[8][128];
    __shared__ float Gs[128];
    __shared__ float Red[128 * 16];

    int tid    = threadIdx.x;
    int b      = blockIdx.z;
    int n_base = blockIdx.x * 128;
    int o_base = blockIdx.y * 128;
    int mi = (tid >> 4) << 3;   // 0..120
    int ni = (tid & 15) << 3;   // 0..120

    float acc[8][8];
#pragma unroll
    for (int i = 0; i < 8; i++)
#pragma unroll
        for (int j = 0; j < 8; j++) acc[i][j] = 0.f;

    const float* xb = x + (size_t)b * CIN * NP;

    int lin = tid * 4;
    int lci = lin >> 7;     // 0..7  (row in 8-deep smem tile)
    int lj  = lin & 127;    // 0..124 step 4

    for (int k = 0; k < KT; k++) {
        int off = k * DILT - PADT;
        __syncthreads();
        if (tid < 128) Gs[tid] = g_gw[((size_t)b * KT + k) * NP + n_base + tid];
        __syncthreads();

        for (int cc = 0; cc < CIN; cc += 8) {
            // stage A: W^T[k][cc+lci][o_base+lj..+3]  (coalesced)
            float4 w4 = *(const float4*)&g_Wt[((size_t)k * CIN + cc + lci) * COUT + o_base + lj];
            *(float4*)&As[lci][lj] = w4;

            // stage B: x[b][cc+lci][n+off] * gate  (coalesced in n, boundary-guarded)
            const float* xr = xb + (size_t)(cc + lci) * NP;
            int src = n_base + lj + off;
            float v0 = (src + 0 >= 0 && src + 0 < NP) ? xr[src + 0] : 0.f;
            float v1 = (src + 1 >= 0 && src + 1 < NP) ? xr[src + 1] : 0.f;
            float v2 = (src + 2 >= 0 && src + 2 < NP) ? xr[src + 2] : 0.f;
            float v3 = (src + 3 >= 0 && src + 3 < NP) ? xr[src + 3] : 0.f;
            Bs[lci][lj + 0] = v0 * Gs[lj + 0];
            Bs[lci][lj + 1] = v1 * Gs[lj + 1];
            Bs[lci][lj + 2] = v2 * Gs[lj + 2];
            Bs[lci][lj + 3] = v3 * Gs[lj + 3];
            __syncthreads();

#pragma unroll
            for (int kc = 0; kc < 8; kc++) {
                float a[8], bv[8];
                *(float4*)&a[0]  = *(const float4*)&As[kc][mi];
                *(float4*)&a[4]  = *(const float4*)&As[kc][mi + 4];
                *(float4*)&bv[0] = *(const float4*)&Bs[kc][ni];
                *(float4*)&bv[4] = *(const float4*)&Bs[kc][ni + 4];
#pragma unroll
                for (int i = 0; i < 8; i++)
#pragma unroll
                    for (int j = 0; j < 8; j++)
                        acc[i][j] += a[i] * bv[j];
            }
            __syncthreads();
        }
    }

    // + bias (pre-BN, matches reference)
#pragma unroll
    for (int i = 0; i < 8; i++) {
        float bi = bias[o_base + mi + i];
#pragma unroll
        for (int j = 0; j < 8; j++) acc[i][j] += bi;
    }

    // write pre-BN conv result
#pragma unroll
    for (int i = 0; i < 8; i++) {
        float* orow = out + ((size_t)b * COUT + o_base + mi + i) * NP + n_base + ni;
        *(float4*)&orow[0] = make_float4(acc[i][0], acc[i][1], acc[i][2], acc[i][3]);
        *(float4*)&orow[4] = make_float4(acc[i][4], acc[i][5], acc[i][6], acc[i][7]);
    }

    // per-channel sum / sumsq partial reductions -> global atomics
    int lane16 = tid & 15;
#pragma unroll
    for (int i = 0; i < 8; i++) {
        float s = 0.f;
#pragma unroll
        for (int j = 0; j < 8; j++) s += acc[i][j];
        Red[(mi + i) * 16 + lane16] = s;
    }
    __syncthreads();
    if (tid < 128) {
        float s = 0.f;
#pragma unroll
        for (int t = 0; t < 16; t++) s += Red[tid * 16 + t];
        atomicAdd(&g_sum[o_base + tid], s);
    }
    __syncthreads();
#pragma unroll
    for (int i = 0; i < 8; i++) {
        float s = 0.f;
#pragma unroll
        for (int j = 0; j < 8; j++) s += acc[i][j] * acc[i][j];
        Red[(mi + i) * 16 + lane16] = s;
    }
    __syncthreads();
    if (tid < 128) {
        float s = 0.f;
#pragma unroll
        for (int t = 0; t < 16; t++) s += Red[tid * 16 + t];
        atomicAdd(&g_sumsq[o_base + tid], s);
    }
}

// ---------------- kernel 4: finalize BN stats ----------------
__global__ void stats_kernel(const float* __restrict__ gamma,
                             const float* __restrict__ beta) {
    int c = threadIdx.x;
    const float inv_n = 1.0f / (float)(BB * NP);
    float mean = g_sum[c] * inv_n;
    float var  = g_sumsq[c] * inv_n - mean * mean;
    float inv  = 1.0f / sqrtf(var + 1e-5f);
    float sc   = gamma[c] * inv;
    g_scale[c] = sc;
    g_shift[c] = beta[c] - mean * sc;
}

// ---------------- kernel 5: apply BN + ReLU in place ----------------
__global__ void apply_kernel(float* __restrict__ out) {
    size_t i4 = (size_t)blockIdx.x * blockDim.x + threadIdx.x;  // float4 index
    float4 v = ((float4*)out)[i4];
    int o = (int)((i4 * 4) >> 13) & (COUT - 1);   // NP = 8192 = 2^13
    float s = g_scale[o], t = g_shift[o];
    v.x = fmaxf(v.x * s + t, 0.f);
    v.y = fmaxf(v.y * s + t, 0.f);
    v.z = fmaxf(v.z * s + t, 0.f);
    v.w = fmaxf(v.w * s + t, 0.f);
    ((float4*)out)[i4] = v;
}

// ---------------- launch ----------------
extern "C" void kernel_launch(void* const* d_in, const int* in_sizes, int n_in,
                              void* d_out, int out_size) {
    const float* x      = (const float*)d_in[0];
    const float* coords = (const float*)d_in[1];
    const float* rot    = (const float*)d_in[2];
    const float* dist   = (const float*)d_in[3];
    const float* W      = (const float*)d_in[4];
    const float* bias   = (const float*)d_in[5];
    const float* gamma  = (const float*)d_in[6];
    const float* beta   = (const float*)d_in[7];
    float* out = (float*)d_out;

    zero_sums_kernel<<<1, 256>>>();
    gweight_kernel<<<dim3(NP / 256, BB), 256>>>(coords, rot, dist);
    wtrans_kernel<<<(COUT * CIN * KT + 255) / 256, 256>>>(W);
    conv_kernel<<<dim3(NP / 128, COUT / 128, BB), 256>>>(x, bias, out);
    stats_kernel<<<1, 256>>>(gamma, beta);
    apply_kernel<<<(BB * COUT * NP / 4) / 256, 256>>>(out);
}

// round 3
// speedup vs baseline: 2.7732x; 2.7732x over previous
#include <cuda_runtime.h>
#include <cuda_bf16.h>
#include <cstdint>
#include <math.h>

#define BB    8
#define CIN   256
#define COUT  256
#define NP    8192
#define KT    9
#define DILT  6
#define PADT  24
#define NCHUNK 36          // (KT * CIN) / 64

// ---------------- device scratch ----------------
__device__ float   g_gw[BB * KT * NP];              // gate weights [b][k][n]
__device__ uint8_t g_A8[2 * NCHUNK * 2 * 16384];    // pre-swizzled split W tiles
__device__ float   g_sum[COUT];
__device__ float   g_sumsq[COUT];
__device__ float   g_scale[COUT];
__device__ float   g_shift[COUT];

// ---------------- helpers ----------------
__device__ __forceinline__ uint32_t smem_u32(const void* p) {
    uint32_t a;
    asm("{ .reg .u64 t; cvta.to.shared.u64 t, %1; cvt.u32.u64 %0, t; }" : "=r"(a) : "l"(p));
    return a;
}
#define SW128(off) ((off) ^ (((off) >> 3) & 0x70))

__device__ __forceinline__ void cp16(uint32_t dst, const void* src) {
    asm volatile("cp.async.cg.shared.global [%0], [%1], 16;" :: "r"(dst), "l"(src));
}
__device__ __forceinline__ void ldsm_x4(uint32_t* r, uint32_t addr) {
    asm volatile("ldmatrix.sync.aligned.m8n8.x4.shared.b16 {%0,%1,%2,%3}, [%4];"
        : "=r"(r[0]), "=r"(r[1]), "=r"(r[2]), "=r"(r[3]) : "r"(addr));
}
__device__ __forceinline__ void ldsm_x2t(uint32_t& r0, uint32_t& r1, uint32_t addr) {
    asm volatile("ldmatrix.sync.aligned.m8n8.x2.trans.shared.b16 {%0,%1}, [%2];"
        : "=r"(r0), "=r"(r1) : "r"(addr));
}
__device__ __forceinline__ void mma16816(float* c, const uint32_t* a, uint32_t b0, uint32_t b1) {
    asm volatile(
        "mma.sync.aligned.m16n8k16.row.col.f32.bf16.bf16.f32 "
        "{%0,%1,%2,%3}, {%4,%5,%6,%7}, {%8,%9}, {%0,%1,%2,%3};"
        : "+f"(c[0]), "+f"(c[1]), "+f"(c[2]), "+f"(c[3])
        : "r"(a[0]), "r"(a[1]), "r"(a[2]), "r"(a[3]), "r"(b0), "r"(b1));
}

// ---------------- kernel 0: zero stat accumulators ----------------
__global__ void zero_sums_kernel() {
    int t = threadIdx.x;
    g_sum[t] = 0.f;
    g_sumsq[t] = 0.f;
}

// ---------------- kernel 1: tap gate weights ----------------
__global__ void gweight_kernel(const float* __restrict__ coords,
                               const float* __restrict__ rot,
                               const float* __restrict__ dist) {
    int n = blockIdx.x * blockDim.x + threadIdx.x;
    int b = blockIdx.y;
    const float* cb = coords + (size_t)b * 3 * NP;
    const float* rb = rot    + (size_t)b * 3 * NP;

    float c0x = cb[n], c0y = cb[NP + n], c0z = cb[2 * NP + n];
    float r0x = rb[n], r0y = rb[NP + n], r0z = rb[2 * NP + n];
    float d0  = dist[(size_t)b * NP + n];
    float r0sq = r0x * r0x + r0y * r0y + r0z * r0z;

#pragma unroll
    for (int k = 0; k < KT; k++) {
        int j = n + k * DILT - PADT;
        float cjx = 0.f, cjy = 0.f, cjz = 0.f;
        float rjx = 0.f, rjy = 0.f, rjz = 0.f;
        float dj  = 0.f;
        if (j >= 0 && j < NP) {
            cjx = cb[j]; cjy = cb[NP + j]; cjz = cb[2 * NP + j];
            rjx = rb[j]; rjy = rb[NP + j]; rjz = rb[2 * NP + j];
            dj  = dist[(size_t)b * NP + j];
        }
        float dx = c0x - cjx, dy = c0y - cjy, dz = c0z - cjz;
        float dc = dx * dx + dy * dy + dz * dz;
        float dd = (d0 - dj) * (d0 - dj);
        float g  = expf(-0.5f * (dc + dd));
        float num  = r0x * rjx + r0y * rjy + r0z * rjz;
        float rjsq = rjx * rjx + rjy * rjy + rjz * rjz;
        float den  = sqrtf(r0sq * rjsq) + 1e-8f;
        g_gw[((size_t)b * KT + k) * NP + n] = g * fabsf(num / den);
    }
}

// ---------------- kernel 2: split + pre-swizzle W ----------------
// Layout: [otile 2][chunk 36][hi 16KB | lo 16KB]; rows = o_in (128B = 64 kc x bf16), SW128.
__global__ void wsplit_kernel(const float* __restrict__ W) {
    int idx = blockIdx.x * 256 + threadIdx.x;
    if (idx >= 2 * NCHUNK * 128 * 64) return;
    int kc    = idx & 63;
    int t     = idx >> 6;
    int o_in  = t & 127;
    int t2    = t >> 7;
    int chunk = t2 % NCHUNK;
    int otile = t2 / NCHUNK;
    int k = chunk >> 2;
    int c = ((chunk & 3) << 6) + kc;
    int o = (otile << 7) + o_in;
    float val = W[((size_t)o * CIN + c) * KT + k];
    __nv_bfloat16 h = __float2bfloat16(val);
    __nv_bfloat16 l = __float2bfloat16(val - __bfloat162float(h));
    uint32_t sw = SW128((uint32_t)(o_in * 128 + kc * 2));
    size_t tb = (size_t)(otile * NCHUNK + chunk) * 32768;
    *(uint16_t*)&g_A8[tb + sw]         = __bfloat16_as_ushort(h);
    *(uint16_t*)&g_A8[tb + 16384 + sw] = __bfloat16_as_ushort(l);
}

// ---------------- SMEM layout ----------------
#define OFF_A   0          // 2 bufs x (hi 16KB + lo 16KB) = 65536
#define OFF_B   65536      // 2 bufs x (hi 16KB + lo 16KB) = 65536
#define OFF_SX  131072     // fp32 staging 64 x 132 floats = 33792
#define OFF_ST  164864     // stats: 256 floats
#define SMEM_TOTAL 165888

// pass2: transpose-free bf16 split; Sx[kc][n] -> B[kc][n] bf16 (swizzled rows of 256B)
__device__ __forceinline__ void pass2(char* smem, uint32_t bb, const float* Sx, int tid) {
#pragma unroll
    for (int it = 0; it < 8; it++) {
        int idx = tid + it * 256;
        int row = idx >> 5;
        int j4  = idx & 31;
        float4 v = *(const float4*)&Sx[row * 132 + j4 * 4];
        __nv_bfloat162 h01 = __float22bfloat162_rn(make_float2(v.x, v.y));
        __nv_bfloat162 h23 = __float22bfloat162_rn(make_float2(v.z, v.w));
        float2 hf01 = __bfloat1622float2(h01);
        float2 hf23 = __bfloat1622float2(h23);
        __nv_bfloat162 l01 = __float22bfloat162_rn(make_float2(v.x - hf01.x, v.y - hf01.y));
        __nv_bfloat162 l23 = __float22bfloat162_rn(make_float2(v.z - hf23.x, v.w - hf23.y));
        uint32_t off = (uint32_t)(row * 256) + (((uint32_t)(8 * j4)) ^ ((uint32_t)(row & 7) << 4));
        *(uint2*)(smem + bb + off)         = make_uint2(*(uint32_t*)&h01, *(uint32_t*)&h23);
        *(uint2*)(smem + bb + 16384 + off) = make_uint2(*(uint32_t*)&l01, *(uint32_t*)&l23);
    }
}

// ---------------- kernel 3: HMMA fused gated dilated conv ----------------
__global__ void __launch_bounds__(256, 1) conv3_kernel(
    const float* __restrict__ x,
    const float* __restrict__ bias,
    float* __restrict__ out) {

    extern __shared__ __align__(16) char smem[];
    const uint32_t sbase = smem_u32(smem);
    float* Sx  = (float*)(smem + OFF_SX);
    float* bst = (float*)(smem + OFF_ST);

    const int tid  = threadIdx.x;
    const int lane = tid & 31;
    const int wid  = tid >> 5;
    const int wm = wid & 3;           // warp m 0..3 (32 rows each)
    const int wn = wid >> 2;          // warp n 0..1 (64 cols each)
    const int g  = lane >> 2;
    const int tg = lane & 3;

    const int b      = blockIdx.z;
    const int n_base = blockIdx.x * 128;
    const int otile  = blockIdx.y;
    const int o_base = otile * 128;

    const float*   xb   = x + (size_t)b * CIN * NP;
    const uint8_t* Asrc = g_A8 + (size_t)otile * NCHUNK * 32768;

    bst[tid] = 0.f;

    // ldmatrix lane-address components
    const int a_row = wm * 32 + ((lane >> 3) & 1) * 8 + (lane & 7);
    const int a_kb  = ((lane >> 4) & 1) * 16;
    const int b_kcl = lane & 15;
    const int ncol  = tid & 127;
    const int row0  = tid >> 7;

    float acc[2][8][4];
#pragma unroll
    for (int mt = 0; mt < 2; mt++)
#pragma unroll
        for (int nt = 0; nt < 8; nt++)
#pragma unroll
            for (int r = 0; r < 4; r++) acc[mt][nt][r] = 0.f;

    // ---- prologue: stage chunk 0 into buf 0 ----
    float gv = g_gw[((size_t)b * KT) * NP + n_base + ncol];
    {
        const int src = n_base - PADT + ncol;
        const bool ok = (src >= 0 && src < NP);
#pragma unroll
        for (int it = 0; it < 32; it++) {
            int row = row0 + it * 2;
            float v = ok ? xb[(size_t)row * NP + src] : 0.f;
            Sx[row * 132 + ncol] = v * gv;
        }
#pragma unroll
        for (int q = 0; q < 8; q++)
            cp16(sbase + OFF_A + tid * 16 + q * 4096, Asrc + tid * 16 + q * 4096);
        asm volatile("cp.async.commit_group;");
        __syncthreads();
        pass2(smem, OFF_B, Sx, tid);
        asm volatile("cp.async.wait_group 0;" ::: "memory");
        __syncthreads();
    }

    // ---- mainloop ----
    for (int i = 0; i < NCHUNK; i++) {
        const int  cur = i & 1;
        const int  nxt = cur ^ 1;
        const bool hn  = (i + 1 < NCHUNK);
        float vreg[32];

        if (hn) {
            const int s = i + 1;
            if ((s & 3) == 0)
                gv = g_gw[((size_t)b * KT + (s >> 2)) * NP + n_base + ncol];
            const int off = (s >> 2) * DILT - PADT;
            const int c0  = (s & 3) << 6;
            const int src = n_base + off + ncol;
            const bool ok = (src >= 0 && src < NP);
            const float* xc = xb + (size_t)c0 * NP + src;
#pragma unroll
            for (int it = 0; it < 32; it++)
                vreg[it] = ok ? xc[(size_t)(row0 + it * 2) * NP] : 0.f;
            const uint8_t* as = Asrc + (size_t)s * 32768 + tid * 16;
            const uint32_t ad = sbase + OFF_A + nxt * 32768 + tid * 16;
#pragma unroll
            for (int q = 0; q < 8; q++) cp16(ad + q * 4096, as + q * 4096);
            asm volatile("cp.async.commit_group;");
        }

        // compute chunk i
        {
            const uint32_t Ab = sbase + OFF_A + cur * 32768;
            const uint32_t Bb = sbase + OFF_B + cur * 32768;
#pragma unroll
            for (int ks = 0; ks < 4; ks++) {
                uint32_t ah[2][4], al[2][4];
#pragma unroll
                for (int mt = 0; mt < 2; mt++) {
                    uint32_t byte = (uint32_t)((a_row + mt * 16) * 128 + ks * 32 + a_kb);
                    uint32_t sw = SW128(byte);
                    ldsm_x4(ah[mt], Ab + sw);
                    ldsm_x4(al[mt], Ab + 16384 + sw);
                }
                const int kc = ks * 16 + b_kcl;
                const uint32_t kb = (uint32_t)kc * 256;
                const uint32_t xm = ((uint32_t)kc & 7) << 4;
#pragma unroll
                for (int nt = 0; nt < 8; nt++) {
                    const uint32_t n2  = (uint32_t)(wn * 64 + nt * 8) * 2;
                    const uint32_t ofs = kb + (n2 ^ xm);
                    uint32_t bh0, bh1, bl0, bl1;
                    ldsm_x2t(bh0, bh1, Bb + ofs);
                    ldsm_x2t(bl0, bl1, Bb + 16384 + ofs);
#pragma unroll
                    for (int mt = 0; mt < 2; mt++) {
                        mma16816(acc[mt][nt], ah[mt], bh0, bh1);
                        mma16816(acc[mt][nt], ah[mt], bl0, bl1);
                        mma16816(acc[mt][nt], al[mt], bh0, bh1);
                    }
                }
            }
        }

        if (hn) {
#pragma unroll
            for (int it = 0; it < 32; it++)
                Sx[(row0 + it * 2) * 132 + ncol] = vreg[it] * gv;
            __syncthreads();
            pass2(smem, OFF_B + nxt * 32768, Sx, tid);
            asm volatile("cp.async.wait_group 0;" ::: "memory");
        }
        __syncthreads();
    }

    // ---- epilogue: bias, store, BN partial stats ----
    float s4[4] = {0.f, 0.f, 0.f, 0.f}, q4[4] = {0.f, 0.f, 0.f, 0.f};
#pragma unroll
    for (int mt = 0; mt < 2; mt++) {
        const int r0v = wm * 32 + mt * 16 + g;
        const int r1v = r0v + 8;
        const float b0v = bias[o_base + r0v];
        const float b1v = bias[o_base + r1v];
        float* p0 = out + ((size_t)b * COUT + o_base + r0v) * NP + n_base + wn * 64 + 2 * tg;
        float* p1 = out + ((size_t)b * COUT + o_base + r1v) * NP + n_base + wn * 64 + 2 * tg;
#pragma unroll
        for (int nt = 0; nt < 8; nt++) {
            float v0 = acc[mt][nt][0] + b0v;
            float v1 = acc[mt][nt][1] + b0v;
            float v2 = acc[mt][nt][2] + b1v;
            float v3 = acc[mt][nt][3] + b1v;
            *(float2*)(p0 + nt * 8) = make_float2(v0, v1);
            *(float2*)(p1 + nt * 8) = make_float2(v2, v3);
            s4[mt * 2 + 0] += v0 + v1;  q4[mt * 2 + 0] += v0 * v0 + v1 * v1;
            s4[mt * 2 + 1] += v2 + v3;  q4[mt * 2 + 1] += v2 * v2 + v3 * v3;
        }
    }
#pragma unroll
    for (int r = 0; r < 4; r++) {
        float s = s4[r], q = q4[r];
        s += __shfl_xor_sync(0xffffffffu, s, 1);
        s += __shfl_xor_sync(0xffffffffu, s, 2);
        q += __shfl_xor_sync(0xffffffffu, q, 1);
        q += __shfl_xor_sync(0xffffffffu, q, 2);
        if (tg == 0) {
            int lr = wm * 32 + (r >> 1) * 16 + (r & 1) * 8 + g;
            atomicAdd(&bst[lr], s);
            atomicAdd(&bst[128 + lr], q);
        }
    }
    __syncthreads();
    if (tid < 128) {
        atomicAdd(&g_sum[o_base + tid],   bst[tid]);
        atomicAdd(&g_sumsq[o_base + tid], bst[128 + tid]);
    }
}

// ---------------- kernel 4: finalize BN stats ----------------
__global__ void stats_kernel(const float* __restrict__ gamma,
                             const float* __restrict__ beta) {
    int c = threadIdx.x;
    const float inv_n = 1.0f / (float)(BB * NP);
    float mean = g_sum[c] * inv_n;
    float var  = g_sumsq[c] * inv_n - mean * mean;
    float inv  = 1.0f / sqrtf(var + 1e-5f);
    float sc   = gamma[c] * inv;
    g_scale[c] = sc;
    g_shift[c] = beta[c] - mean * sc;
}

// ---------------- kernel 5: apply BN + ReLU ----------------
__global__ void apply_kernel(float* __restrict__ out) {
    size_t i4 = (size_t)blockIdx.x * blockDim.x + threadIdx.x;
    float4 v = ((float4*)out)[i4];
    int o = (int)((i4 * 4) >> 13) & (COUT - 1);
    float s = g_scale[o], t = g_shift[o];
    v.x = fmaxf(v.x * s + t, 0.f);
    v.y = fmaxf(v.y * s + t, 0.f);
    v.z = fmaxf(v.z * s + t, 0.f);
    v.w = fmaxf(v.w * s + t, 0.f);
    ((float4*)out)[i4] = v;
}

// ---------------- launch ----------------
extern "C" void kernel_launch(void* const* d_in, const int* in_sizes, int n_in,
                              void* d_out, int out_size) {
    const float* x      = (const float*)d_in[0];
    const float* coords = (const float*)d_in[1];
    const float* rot    = (const float*)d_in[2];
    const float* dist   = (const float*)d_in[3];
    const float* W      = (const float*)d_in[4];
    const float* bias   = (const float*)d_in[5];
    const float* gamma  = (const float*)d_in[6];
    const float* beta   = (const float*)d_in[7];
    float* out = (float*)d_out;

    static int configured = 0;
    if (!configured) {
        cudaFuncSetAttribute(conv3_kernel, cudaFuncAttributeMaxDynamicSharedMemorySize, SMEM_TOTAL);
        configured = 1;
    }

    zero_sums_kernel<<<1, 256>>>();
    gweight_kernel<<<dim3(NP / 256, BB), 256>>>(coords, rot, dist);
    wsplit_kernel<<<(2 * NCHUNK * 128 * 64 + 255) / 256, 256>>>(W);
    conv3_kernel<<<dim3(NP / 128, COUT / 128, BB), 256, SMEM_TOTAL>>>(x, bias, out);
    stats_kernel<<<1, 256>>>(gamma, beta);
    apply_kernel<<<(BB * COUT * NP / 4) / 256, 256>>>(out);
}

// round 4
// speedup vs baseline: 3.3152x; 1.1954x over previous
#include <cuda_runtime.h>
#include <cuda_fp16.h>
#include <cstdint>
#include <math.h>

#define BB    8
#define CIN   256
#define COUT  256
#define NP    8192
#define KT    9
#define DILT  6
#define PADT  24
#define NCHUNK 36          // (KT * CIN) / 64

// ---------------- device scratch ----------------
__device__ float   g_gw[BB * KT * NP];              // gate weights [b][k][n]
__device__ uint8_t g_A8[2 * NCHUNK * 16384];        // pre-swizzled fp16 W tiles
__device__ float   g_sum[COUT];
__device__ float   g_sumsq[COUT];
__device__ float   g_scale[COUT];
__device__ float   g_shift[COUT];

// ---------------- helpers ----------------
__device__ __forceinline__ uint32_t smem_u32(const void* p) {
    uint32_t a;
    asm("{ .reg .u64 t; cvta.to.shared.u64 t, %1; cvt.u32.u64 %0, t; }" : "=r"(a) : "l"(p));
    return a;
}
#define SW128(off) ((off) ^ (((off) >> 3) & 0x70))

__device__ __forceinline__ void cp16(uint32_t dst, const void* src) {
    asm volatile("cp.async.cg.shared.global [%0], [%1], 16;" :: "r"(dst), "l"(src));
}
__device__ __forceinline__ void ldsm_x4(uint32_t* r, uint32_t addr) {
    asm volatile("ldmatrix.sync.aligned.m8n8.x4.shared.b16 {%0,%1,%2,%3}, [%4];"
        : "=r"(r[0]), "=r"(r[1]), "=r"(r[2]), "=r"(r[3]) : "r"(addr));
}
__device__ __forceinline__ void ldsm_x2t(uint32_t& r0, uint32_t& r1, uint32_t addr) {
    asm volatile("ldmatrix.sync.aligned.m8n8.x2.trans.shared.b16 {%0,%1}, [%2];"
        : "=r"(r0), "=r"(r1) : "r"(addr));
}
__device__ __forceinline__ void mma16816(float* c, const uint32_t* a, uint32_t b0, uint32_t b1) {
    asm volatile(
        "mma.sync.aligned.m16n8k16.row.col.f32.f16.f16.f32 "
        "{%0,%1,%2,%3}, {%4,%5,%6,%7}, {%8,%9}, {%0,%1,%2,%3};"
        : "+f"(c[0]), "+f"(c[1]), "+f"(c[2]), "+f"(c[3])
        : "r"(a[0]), "r"(a[1]), "r"(a[2]), "r"(a[3]), "r"(b0), "r"(b1));
}

// ---------------- kernel 0 ----------------
__global__ void zero_sums_kernel() {
    int t = threadIdx.x;
    g_sum[t] = 0.f;
    g_sumsq[t] = 0.f;
}

// ---------------- kernel 1: tap gate weights ----------------
__global__ void gweight_kernel(const float* __restrict__ coords,
                               const float* __restrict__ rot,
                               const float* __restrict__ dist) {
    int n = blockIdx.x * blockDim.x + threadIdx.x;
    int b = blockIdx.y;
    const float* cb = coords + (size_t)b * 3 * NP;
    const float* rb = rot    + (size_t)b * 3 * NP;

    float c0x = cb[n], c0y = cb[NP + n], c0z = cb[2 * NP + n];
    float r0x = rb[n], r0y = rb[NP + n], r0z = rb[2 * NP + n];
    float d0  = dist[(size_t)b * NP + n];
    float r0sq = r0x * r0x + r0y * r0y + r0z * r0z;

#pragma unroll
    for (int k = 0; k < KT; k++) {
        int j = n + k * DILT - PADT;
        float cjx = 0.f, cjy = 0.f, cjz = 0.f;
        float rjx = 0.f, rjy = 0.f, rjz = 0.f;
        float dj  = 0.f;
        if (j >= 0 && j < NP) {
            cjx = cb[j]; cjy = cb[NP + j]; cjz = cb[2 * NP + j];
            rjx = rb[j]; rjy = rb[NP + j]; rjz = rb[2 * NP + j];
            dj  = dist[(size_t)b * NP + j];
        }
        float dx = c0x - cjx, dy = c0y - cjy, dz = c0z - cjz;
        float dc = dx * dx + dy * dy + dz * dz;
        float dd = (d0 - dj) * (d0 - dj);
        float g  = expf(-0.5f * (dc + dd));
        float num  = r0x * rjx + r0y * rjy + r0z * rjz;
        float rjsq = rjx * rjx + rjy * rjy + rjz * rjz;
        float den  = sqrtf(r0sq * rjsq) + 1e-8f;
        g_gw[((size_t)b * KT + k) * NP + n] = g * fabsf(num / den);
    }
}

// ---------------- kernel 2: fp16 pre-swizzled W ----------------
// Layout: [otile 2][chunk 36][16KB]; rows = o_in (128B = 64 kc x fp16), SW128.
__global__ void wsplit_kernel(const float* __restrict__ W) {
    int idx = blockIdx.x * 256 + threadIdx.x;
    if (idx >= 2 * NCHUNK * 128 * 64) return;
    int kc    = idx & 63;
    int t     = idx >> 6;
    int o_in  = t & 127;
    int t2    = t >> 7;
    int chunk = t2 % NCHUNK;
    int otile = t2 / NCHUNK;
    int k = chunk >> 2;
    int c = ((chunk & 3) << 6) + kc;
    int o = (otile << 7) + o_in;
    float val = W[((size_t)o * CIN + c) * KT + k];
    uint32_t sw = SW128((uint32_t)(o_in * 128 + kc * 2));
    size_t tb = (size_t)(otile * NCHUNK + chunk) * 16384;
    *(__half*)&g_A8[tb + sw] = __float2half(val);
}

// ---------------- SMEM layout ----------------
#define OFF_A   0          // 2 bufs x 16KB = 32768
#define OFF_B   32768      // 2 bufs x (hi 16KB + lo 16KB) = 65536
#define OFF_ST  98304      // stats: 256 floats
#define SMEM_TOTAL 99328

// stage chunk s of B: gated x, fp16 hi/lo split, straight into [kc][n] swizzled tile
__device__ __forceinline__ void stageB(char* smem, uint32_t bb,
                                       const float* __restrict__ xb, int b,
                                       int n_base, int s, int tid) {
    const int kk  = s >> 2;
    const int off = kk * DILT - PADT;
    const int c0  = (s & 3) << 6;
    const float4* gk4 = (const float4*)(g_gw + ((size_t)b * KT + kk) * NP + n_base);
    const bool interior = (n_base + off >= 0) && (n_base + off + 127 < NP);

#pragma unroll
    for (int it = 0; it < 8; it++) {
        int idx = tid + it * 256;
        int row = idx >> 5;         // kc row 0..63
        int j4  = idx & 31;
        int nn  = j4 << 2;
        const float* xr = xb + (size_t)(c0 + row) * NP;
        int src = n_base + off + nn;
        float4 v;
        if (interior) {
            float2 p0 = *(const float2*)&xr[src];
            float2 p1 = *(const float2*)&xr[src + 2];
            v = make_float4(p0.x, p0.y, p1.x, p1.y);
        } else {
            v.x = (src + 0 >= 0 && src + 0 < NP) ? xr[src + 0] : 0.f;
            v.y = (src + 1 >= 0 && src + 1 < NP) ? xr[src + 1] : 0.f;
            v.z = (src + 2 >= 0 && src + 2 < NP) ? xr[src + 2] : 0.f;
            v.w = (src + 3 >= 0 && src + 3 < NP) ? xr[src + 3] : 0.f;
        }
        float4 g4 = gk4[j4];
        v.x *= g4.x; v.y *= g4.y; v.z *= g4.z; v.w *= g4.w;

        __half2 h01 = __floats2half2_rn(v.x, v.y);
        __half2 h23 = __floats2half2_rn(v.z, v.w);
        float2 f01 = __half22float2(h01);
        float2 f23 = __half22float2(h23);
        __half2 l01 = __floats2half2_rn(v.x - f01.x, v.y - f01.y);
        __half2 l23 = __floats2half2_rn(v.z - f23.x, v.w - f23.y);

        uint32_t ofs = (uint32_t)(row * 256) + (((uint32_t)(nn * 2)) ^ ((uint32_t)(row & 7) << 4));
        *(uint2*)(smem + bb + ofs)         = make_uint2(*(uint32_t*)&h01, *(uint32_t*)&h23);
        *(uint2*)(smem + bb + 16384 + ofs) = make_uint2(*(uint32_t*)&l01, *(uint32_t*)&l23);
    }
}

// ---------------- kernel 3: HMMA fused gated dilated conv ----------------
__global__ void __launch_bounds__(256, 2) conv4_kernel(
    const float* __restrict__ x,
    const float* __restrict__ bias,
    float* __restrict__ out) {

    extern __shared__ __align__(16) char smem[];
    const uint32_t sbase = smem_u32(smem);
    float* bst = (float*)(smem + OFF_ST);

    const int tid  = threadIdx.x;
    const int lane = tid & 31;
    const int wid  = tid >> 5;
    const int wm = wid & 3;
    const int wn = wid >> 2;
    const int g  = lane >> 2;
    const int tg = lane & 3;

    const int b      = blockIdx.z;
    const int n_base = blockIdx.x * 128;
    const int otile  = blockIdx.y;
    const int o_base = otile * 128;

    const float*   xb   = x + (size_t)b * CIN * NP;
    const uint8_t* Asrc = g_A8 + (size_t)otile * NCHUNK * 16384;

    bst[tid] = 0.f;

    const int a_row = wm * 32 + ((lane >> 3) & 1) * 8 + (lane & 7);
    const int a_kb  = ((lane >> 4) & 1) * 16;
    const int b_kcl = lane & 15;

    float acc[2][8][4];
#pragma unroll
    for (int mt = 0; mt < 2; mt++)
#pragma unroll
        for (int nt = 0; nt < 8; nt++)
#pragma unroll
            for (int r = 0; r < 4; r++) acc[mt][nt][r] = 0.f;

    // ---- prologue ----
    {
        const uint8_t* as = Asrc + tid * 16;
        const uint32_t ad = sbase + OFF_A + tid * 16;
#pragma unroll
        for (int q = 0; q < 4; q++) cp16(ad + q * 4096, as + q * 4096);
        asm volatile("cp.async.commit_group;");
        stageB(smem, OFF_B, xb, b, n_base, 0, tid);
    }

    // ---- mainloop ----
    for (int i = 0; i < NCHUNK; i++) {
        const int  cur = i & 1;
        const int  nxt = cur ^ 1;
        const bool hn  = (i + 1 < NCHUNK);

        asm volatile("cp.async.wait_group 0;" ::: "memory");
        __syncthreads();

        if (hn) {
            const uint8_t* as = Asrc + (size_t)(i + 1) * 16384 + tid * 16;
            const uint32_t ad = sbase + OFF_A + nxt * 16384 + tid * 16;
#pragma unroll
            for (int q = 0; q < 4; q++) cp16(ad + q * 4096, as + q * 4096);
            asm volatile("cp.async.commit_group;");
        }

        // compute chunk i
        {
            const uint32_t Ab = sbase + OFF_A + cur * 16384;
            const uint32_t Bb = sbase + OFF_B + cur * 32768;
#pragma unroll
            for (int ks = 0; ks < 4; ks++) {
                uint32_t ah[2][4];
#pragma unroll
                for (int mt = 0; mt < 2; mt++) {
                    uint32_t byte = (uint32_t)((a_row + mt * 16) * 128 + ks * 32 + a_kb);
                    ldsm_x4(ah[mt], Ab + SW128(byte));
                }
                const int kc = ks * 16 + b_kcl;
                const uint32_t kb = (uint32_t)kc * 256;
                const uint32_t xm = ((uint32_t)kc & 7) << 4;
#pragma unroll
                for (int nt = 0; nt < 8; nt++) {
                    const uint32_t n2  = (uint32_t)(wn * 64 + nt * 8) * 2;
                    const uint32_t ofs = kb + (n2 ^ xm);
                    uint32_t bh0, bh1, bl0, bl1;
                    ldsm_x2t(bh0, bh1, Bb + ofs);
                    ldsm_x2t(bl0, bl1, Bb + 16384 + ofs);
#pragma unroll
                    for (int mt = 0; mt < 2; mt++) {
                        mma16816(acc[mt][nt], ah[mt], bh0, bh1);
                        mma16816(acc[mt][nt], ah[mt], bl0, bl1);
                    }
                }
            }
        }

        if (hn) stageB(smem, OFF_B + nxt * 32768, xb, b, n_base, i + 1, tid);
    }

    // ---- epilogue ----
    float s4[4] = {0.f, 0.f, 0.f, 0.f}, q4[4] = {0.f, 0.f, 0.f, 0.f};
#pragma unroll
    for (int mt = 0; mt < 2; mt++) {
        const int r0v = wm * 32 + mt * 16 + g;
        const int r1v = r0v + 8;
        const float b0v = bias[o_base + r0v];
        const float b1v = bias[o_base + r1v];
        float* p0 = out + ((size_t)b * COUT + o_base + r0v) * NP + n_base + wn * 64 + 2 * tg;
        float* p1 = out + ((size_t)b * COUT + o_base + r1v) * NP + n_base + wn * 64 + 2 * tg;
#pragma unroll
        for (int nt = 0; nt < 8; nt++) {
            float v0 = acc[mt][nt][0] + b0v;
            float v1 = acc[mt][nt][1] + b0v;
            float v2 = acc[mt][nt][2] + b1v;
            float v3 = acc[mt][nt][3] + b1v;
            *(float2*)(p0 + nt * 8) = make_float2(v0, v1);
            *(float2*)(p1 + nt * 8) = make_float2(v2, v3);
            s4[mt * 2 + 0] += v0 + v1;  q4[mt * 2 + 0] += v0 * v0 + v1 * v1;
            s4[mt * 2 + 1] += v2 + v3;  q4[mt * 2 + 1] += v2 * v2 + v3 * v3;
        }
    }
#pragma unroll
    for (int r = 0; r < 4; r++) {
        float s = s4[r], q = q4[r];
        s += __shfl_xor_sync(0xffffffffu, s, 1);
        s += __shfl_xor_sync(0xffffffffu, s, 2);
        q += __shfl_xor_sync(0xffffffffu, q, 1);
        q += __shfl_xor_sync(0xffffffffu, q, 2);
        if (tg == 0) {
            int lr = wm * 32 + (r >> 1) * 16 + (r & 1) * 8 + g;
            atomicAdd(&bst[lr], s);
            atomicAdd(&bst[128 + lr], q);
        }
    }
    __syncthreads();
    if (tid < 128) {
        atomicAdd(&g_sum[o_base + tid],   bst[tid]);
        atomicAdd(&g_sumsq[o_base + tid], bst[128 + tid]);
    }
}

// ---------------- kernel 4: finalize BN stats ----------------
__global__ void stats_kernel(const float* __restrict__ gamma,
                             const float* __restrict__ beta) {
    int c = threadIdx.x;
    const float inv_n = 1.0f / (float)(BB * NP);
    float mean = g_sum[c] * inv_n;
    float var  = g_sumsq[c] * inv_n - mean * mean;
    float inv  = 1.0f / sqrtf(var + 1e-5f);
    float sc   = gamma[c] * inv;
    g_scale[c] = sc;
    g_shift[c] = beta[c] - mean * sc;
}

// ---------------- kernel 5: apply BN + ReLU ----------------
__global__ void apply_kernel(float* __restrict__ out) {
    size_t i4 = (size_t)blockIdx.x * blockDim.x + threadIdx.x;
    float4 v = ((float4*)out)[i4];
    int o = (int)((i4 * 4) >> 13) & (COUT - 1);
    float s = g_scale[o], t = g_shift[o];
    v.x = fmaxf(v.x * s + t, 0.f);
    v.y = fmaxf(v.y * s + t, 0.f);
    v.z = fmaxf(v.z * s + t, 0.f);
    v.w = fmaxf(v.w * s + t, 0.f);
    ((float4*)out)[i4] = v;
}

// ---------------- launch ----------------
extern "C" void kernel_launch(void* const* d_in, const int* in_sizes, int n_in,
                              void* d_out, int out_size) {
    const float* x      = (const float*)d_in[0];
    const float* coords = (const float*)d_in[1];
    const float* rot    = (const float*)d_in[2];
    const float* dist   = (const float*)d_in[3];
    const float* W      = (const float*)d_in[4];
    const float* bias   = (const float*)d_in[5];
    const float* gamma  = (const float*)d_in[6];
    const float* beta   = (const float*)d_in[7];
    float* out = (float*)d_out;

    cudaFuncSetAttribute(conv4_kernel, cudaFuncAttributeMaxDynamicSharedMemorySize, SMEM_TOTAL);

    zero_sums_kernel<<<1, 256>>>();
    gweight_kernel<<<dim3(NP / 256, BB), 256>>>(coords, rot, dist);
    wsplit_kernel<<<(2 * NCHUNK * 128 * 64 + 255) / 256, 256>>>(W);
    conv4_kernel<<<dim3(NP / 128, COUT / 128, BB), 256, SMEM_TOTAL>>>(x, bias, out);
    stats_kernel<<<1, 256>>>(gamma, beta);
    apply_kernel<<<(BB * COUT * NP / 4) / 256, 256>>>(out);
}

// round 5
// speedup vs baseline: 4.4312x; 1.3366x over previous
#include <cuda_runtime.h>
#include <cuda_fp16.h>
#include <cstdint>
#include <math.h>

#define BB    8
#define CIN   256
#define COUT  256
#define NP    8192
#define KT    9
#define DILT  6
#define PADT  24
#define NCHUNK 36          // (KT * CIN) / 64

// ---------------- device scratch ----------------
__device__ float   g_gw[BB * KT * NP];              // gate weights [b][k][n]
__device__ uint8_t g_A8[2 * NCHUNK * 16384];        // pre-swizzled fp16 W tiles
__device__ float   g_sum[COUT];
__device__ float   g_sumsq[COUT];
__device__ float   g_scale[COUT];
__device__ float   g_shift[COUT];

// ---------------- helpers ----------------
__device__ __forceinline__ uint32_t smem_u32(const void* p) {
    uint32_t a;
    asm("{ .reg .u64 t; cvta.to.shared.u64 t, %1; cvt.u32.u64 %0, t; }" : "=r"(a) : "l"(p));
    return a;
}
#define SW128(off) ((off) ^ (((off) >> 3) & 0x70))

__device__ __forceinline__ void cp16(uint32_t dst, const void* src) {
    asm volatile("cp.async.cg.shared.global [%0], [%1], 16;" :: "r"(dst), "l"(src));
}
__device__ __forceinline__ void ldsm_x4(uint32_t* r, uint32_t addr) {
    asm volatile("ldmatrix.sync.aligned.m8n8.x4.shared.b16 {%0,%1,%2,%3}, [%4];"
        : "=r"(r[0]), "=r"(r[1]), "=r"(r[2]), "=r"(r[3]) : "r"(addr));
}
__device__ __forceinline__ void ldsm_x4t(uint32_t* r, uint32_t addr) {
    asm volatile("ldmatrix.sync.aligned.m8n8.x4.trans.shared.b16 {%0,%1,%2,%3}, [%4];"
        : "=r"(r[0]), "=r"(r[1]), "=r"(r[2]), "=r"(r[3]) : "r"(addr));
}
__device__ __forceinline__ void mma16816(float* c, const uint32_t* a, uint32_t b0, uint32_t b1) {
    asm volatile(
        "mma.sync.aligned.m16n8k16.row.col.f32.f16.f16.f32 "
        "{%0,%1,%2,%3}, {%4,%5,%6,%7}, {%8,%9}, {%0,%1,%2,%3};"
        : "+f"(c[0]), "+f"(c[1]), "+f"(c[2]), "+f"(c[3])
        : "r"(a[0]), "r"(a[1]), "r"(a[2]), "r"(a[3]), "r"(b0), "r"(b1));
}

// ---------------- kernel 0 ----------------
__global__ void zero_sums_kernel() {
    int t = threadIdx.x;
    g_sum[t] = 0.f;
    g_sumsq[t] = 0.f;
}

// ---------------- kernel 1: tap gate weights ----------------
__global__ void gweight_kernel(const float* __restrict__ coords,
                               const float* __restrict__ rot,
                               const float* __restrict__ dist) {
    int n = blockIdx.x * blockDim.x + threadIdx.x;
    int b = blockIdx.y;
    const float* cb = coords + (size_t)b * 3 * NP;
    const float* rb = rot    + (size_t)b * 3 * NP;

    float c0x = cb[n], c0y = cb[NP + n], c0z = cb[2 * NP + n];
    float r0x = rb[n], r0y = rb[NP + n], r0z = rb[2 * NP + n];
    float d0  = dist[(size_t)b * NP + n];
    float r0sq = r0x * r0x + r0y * r0y + r0z * r0z;

#pragma unroll
    for (int k = 0; k < KT; k++) {
        int j = n + k * DILT - PADT;
        float cjx = 0.f, cjy = 0.f, cjz = 0.f;
        float rjx = 0.f, rjy = 0.f, rjz = 0.f;
        float dj  = 0.f;
        if (j >= 0 && j < NP) {
            cjx = cb[j]; cjy = cb[NP + j]; cjz = cb[2 * NP + j];
            rjx = rb[j]; rjy = rb[NP + j]; rjz = rb[2 * NP + j];
            dj  = dist[(size_t)b * NP + j];
        }
        float dx = c0x - cjx, dy = c0y - cjy, dz = c0z - cjz;
        float dc = dx * dx + dy * dy + dz * dz;
        float dd = (d0 - dj) * (d0 - dj);
        float g  = expf(-0.5f * (dc + dd));
        float num  = r0x * rjx + r0y * rjy + r0z * rjz;
        float rjsq = rjx * rjx + rjy * rjy + rjz * rjz;
        float den  = sqrtf(r0sq * rjsq) + 1e-8f;
        g_gw[((size_t)b * KT + k) * NP + n] = g * fabsf(num / den);
    }
}

// ---------------- kernel 2: fp16 pre-swizzled W ----------------
// Layout: [otile 2][chunk 36][16KB]; rows = o_in (128B = 64 kc x fp16), SW128.
__global__ void wsplit_kernel(const float* __restrict__ W) {
    int idx = blockIdx.x * 256 + threadIdx.x;
    if (idx >= 2 * NCHUNK * 128 * 64) return;
    int kc    = idx & 63;
    int t     = idx >> 6;
    int o_in  = t & 127;
    int t2    = t >> 7;
    int chunk = t2 % NCHUNK;
    int otile = t2 / NCHUNK;
    int k = chunk >> 2;
    int c = ((chunk & 3) << 6) + kc;
    int o = (otile << 7) + o_in;
    float val = W[((size_t)o * CIN + c) * KT + k];
    uint32_t sw = SW128((uint32_t)(o_in * 128 + kc * 2));
    size_t tb = (size_t)(otile * NCHUNK + chunk) * 16384;
    *(__half*)&g_A8[tb + sw] = __float2half(val);
}

// ---------------- SMEM layout ----------------
#define OFF_A   0          // 2 bufs x 16KB = 32768
#define OFF_B   32768      // 2 bufs x 16KB = 32768
#define OFF_ST  65536      // stats: 256 floats
#define SMEM_TOTAL 66560

// stage chunk s of B: gated x -> fp16, straight into [kc][n] swizzled tile
__device__ __forceinline__ void stageB(char* smem, uint32_t bb,
                                       const float* __restrict__ xb, int b,
                                       int n_base, int s, int tid) {
    const int kk  = s >> 2;
    const int off = kk * DILT - PADT;
    const int c0  = (s & 3) << 6;
    const float4* gk4 = (const float4*)(g_gw + ((size_t)b * KT + kk) * NP + n_base);
    const bool interior = (n_base + off >= 0) && (n_base + off + 127 < NP);

#pragma unroll
    for (int it = 0; it < 8; it++) {
        int idx = tid + it * 256;
        int row = idx >> 5;         // kc row 0..63
        int j4  = idx & 31;
        int nn  = j4 << 2;
        const float* xr = xb + (size_t)(c0 + row) * NP;
        int src = n_base + off + nn;
        float4 v;
        if (interior) {
            float2 p0 = *(const float2*)&xr[src];
            float2 p1 = *(const float2*)&xr[src + 2];
            v = make_float4(p0.x, p0.y, p1.x, p1.y);
        } else {
            v.x = (src + 0 >= 0 && src + 0 < NP) ? xr[src + 0] : 0.f;
            v.y = (src + 1 >= 0 && src + 1 < NP) ? xr[src + 1] : 0.f;
            v.z = (src + 2 >= 0 && src + 2 < NP) ? xr[src + 2] : 0.f;
            v.w = (src + 3 >= 0 && src + 3 < NP) ? xr[src + 3] : 0.f;
        }
        float4 g4 = gk4[j4];
        __half2 h01 = __floats2half2_rn(v.x * g4.x, v.y * g4.y);
        __half2 h23 = __floats2half2_rn(v.z * g4.z, v.w * g4.w);

        uint32_t ofs = (uint32_t)(row * 256) + (((uint32_t)(nn * 2)) ^ ((uint32_t)(row & 7) << 4));
        *(uint2*)(smem + bb + ofs) = make_uint2(*(uint32_t*)&h01, *(uint32_t*)&h23);
    }
}

// ---------------- kernel 3: HMMA fused gated dilated conv ----------------
__global__ void __launch_bounds__(256, 2) conv5_kernel(
    const float* __restrict__ x,
    const float* __restrict__ bias,
    float* __restrict__ out) {

    extern __shared__ __align__(16) char smem[];
    const uint32_t sbase = smem_u32(smem);
    float* bst = (float*)(smem + OFF_ST);

    const int tid  = threadIdx.x;
    const int lane = tid & 31;
    const int wid  = tid >> 5;
    const int wm = wid & 3;
    const int wn = wid >> 2;
    const int g  = lane >> 2;
    const int tg = lane & 3;

    const int b      = blockIdx.z;
    const int n_base = blockIdx.x * 128;
    const int otile  = blockIdx.y;
    const int o_base = otile * 128;

    const float*   xb   = x + (size_t)b * CIN * NP;
    const uint8_t* Asrc = g_A8 + (size_t)otile * NCHUNK * 16384;

    bst[tid] = 0.f;

    const int a_row   = wm * 32 + ((lane >> 3) & 1) * 8 + (lane & 7);
    const int a_kb    = ((lane >> 4) & 1) * 16;
    const int b_kcl   = lane & 15;
    const int b_nbyte = wn * 128 + ((lane >> 4) << 4);   // bytes within kc row

    float acc[2][8][4];
#pragma unroll
    for (int mt = 0; mt < 2; mt++)
#pragma unroll
        for (int nt = 0; nt < 8; nt++)
#pragma unroll
            for (int r = 0; r < 4; r++) acc[mt][nt][r] = 0.f;

    // ---- prologue ----
    {
        const uint8_t* as = Asrc + tid * 16;
        const uint32_t ad = sbase + OFF_A + tid * 16;
#pragma unroll
        for (int q = 0; q < 4; q++) cp16(ad + q * 4096, as + q * 4096);
        asm volatile("cp.async.commit_group;");
        stageB(smem, OFF_B, xb, b, n_base, 0, tid);
    }

    // ---- mainloop ----
    for (int i = 0; i < NCHUNK; i++) {
        const int  cur = i & 1;
        const int  nxt = cur ^ 1;
        const bool hn  = (i + 1 < NCHUNK);

        asm volatile("cp.async.wait_group 0;" ::: "memory");
        __syncthreads();

        if (hn) {
            const uint8_t* as = Asrc + (size_t)(i + 1) * 16384 + tid * 16;
            const uint32_t ad = sbase + OFF_A + nxt * 16384 + tid * 16;
#pragma unroll
            for (int q = 0; q < 4; q++) cp16(ad + q * 4096, as + q * 4096);
            asm volatile("cp.async.commit_group;");
        }

        // compute chunk i
        {
            const uint32_t Ab = sbase + OFF_A + cur * 16384;
            const uint32_t Bb = sbase + OFF_B + cur * 16384;
#pragma unroll
            for (int ks = 0; ks < 4; ks++) {
                uint32_t ah[2][4];
#pragma unroll
                for (int mt = 0; mt < 2; mt++) {
                    uint32_t byte = (uint32_t)((a_row + mt * 16) * 128 + ks * 32 + a_kb);
                    ldsm_x4(ah[mt], Ab + SW128(byte));
                }
                const int kc = ks * 16 + b_kcl;
                const uint32_t kb = (uint32_t)kc * 256;
                const uint32_t xm = ((uint32_t)kc & 7) << 4;
#pragma unroll
                for (int nt2 = 0; nt2 < 4; nt2++) {
                    uint32_t br[4];
                    const uint32_t nb = (uint32_t)(b_nbyte + nt2 * 32);
                    ldsm_x4t(br, Bb + kb + (nb ^ xm));
#pragma unroll
                    for (int mt = 0; mt < 2; mt++) {
                        mma16816(acc[mt][nt2 * 2 + 0], ah[mt], br[0], br[1]);
                        mma16816(acc[mt][nt2 * 2 + 1], ah[mt], br[2], br[3]);
                    }
                }
            }
        }

        if (hn) stageB(smem, OFF_B + nxt * 16384, xb, b, n_base, i + 1, tid);
    }

    // ---- epilogue ----
    float s4[4] = {0.f, 0.f, 0.f, 0.f}, q4[4] = {0.f, 0.f, 0.f, 0.f};
#pragma unroll
    for (int mt = 0; mt < 2; mt++) {
        const int r0v = wm * 32 + mt * 16 + g;
        const int r1v = r0v + 8;
        const float b0v = bias[o_base + r0v];
        const float b1v = bias[o_base + r1v];
        float* p0 = out + ((size_t)b * COUT + o_base + r0v) * NP + n_base + wn * 64 + 2 * tg;
        float* p1 = out + ((size_t)b * COUT + o_base + r1v) * NP + n_base + wn * 64 + 2 * tg;
#pragma unroll
        for (int nt = 0; nt < 8; nt++) {
            float v0 = acc[mt][nt][0] + b0v;
            float v1 = acc[mt][nt][1] + b0v;
            float v2 = acc[mt][nt][2] + b1v;
            float v3 = acc[mt][nt][3] + b1v;
            *(float2*)(p0 + nt * 8) = make_float2(v0, v1);
            *(float2*)(p1 + nt * 8) = make_float2(v2, v3);
            s4[mt * 2 + 0] += v0 + v1;  q4[mt * 2 + 0] += v0 * v0 + v1 * v1;
            s4[mt * 2 + 1] += v2 + v3;  q4[mt * 2 + 1] += v2 * v2 + v3 * v3;
        }
    }
#pragma unroll
    for (int r = 0; r < 4; r++) {
        float s = s4[r], q = q4[r];
        s += __shfl_xor_sync(0xffffffffu, s, 1);
        s += __shfl_xor_sync(0xffffffffu, s, 2);
        q += __shfl_xor_sync(0xffffffffu, q, 1);
        q += __shfl_xor_sync(0xffffffffu, q, 2);
        if (tg == 0) {
            int lr = wm * 32 + (r >> 1) * 16 + (r & 1) * 8 + g;
            atomicAdd(&bst[lr], s);
            atomicAdd(&bst[128 + lr], q);
        }
    }
    __syncthreads();
    if (tid < 128) {
        atomicAdd(&g_sum[o_base + tid],   bst[tid]);
        atomicAdd(&g_sumsq[o_base + tid], bst[128 + tid]);
    }
}

// ---------------- kernel 4: finalize BN stats ----------------
__global__ void stats_kernel(const float* __restrict__ gamma,
                             const float* __restrict__ beta) {
    int c = threadIdx.x;
    const float inv_n = 1.0f / (float)(BB * NP);
    float mean = g_sum[c] * inv_n;
    float var  = g_sumsq[c] * inv_n - mean * mean;
    float inv  = 1.0f / sqrtf(var + 1e-5f);
    float sc   = gamma[c] * inv;
    g_scale[c] = sc;
    g_shift[c] = beta[c] - mean * sc;
}

// ---------------- kernel 5: apply BN + ReLU ----------------
__global__ void apply_kernel(float* __restrict__ out) {
    size_t i4 = (size_t)blockIdx.x * blockDim.x + threadIdx.x;
    float4 v = ((float4*)out)[i4];
    int o = (int)((i4 * 4) >> 13) & (COUT - 1);
    float s = g_scale[o], t = g_shift[o];
    v.x = fmaxf(v.x * s + t, 0.f);
    v.y = fmaxf(v.y * s + t, 0.f);
    v.z = fmaxf(v.z * s + t, 0.f);
    v.w = fmaxf(v.w * s + t, 0.f);
    ((float4*)out)[i4] = v;
}

// ---------------- launch ----------------
extern "C" void kernel_launch(void* const* d_in, const int* in_sizes, int n_in,
                              void* d_out, int out_size) {
    const float* x      = (const float*)d_in[0];
    const float* coords = (const float*)d_in[1];
    const float* rot    = (const float*)d_in[2];
    const float* dist   = (const float*)d_in[3];
    const float* W      = (const float*)d_in[4];
    const float* bias   = (const float*)d_in[5];
    const float* gamma  = (const float*)d_in[6];
    const float* beta   = (const float*)d_in[7];
    float* out = (float*)d_out;

    cudaFuncSetAttribute(conv5_kernel, cudaFuncAttributeMaxDynamicSharedMemorySize, SMEM_TOTAL);

    zero_sums_kernel<<<1, 256>>>();
    gweight_kernel<<<dim3(NP / 256, BB), 256>>>(coords, rot, dist);
    wsplit_kernel<<<(2 * NCHUNK * 128 * 64 + 255) / 256, 256>>>(W);
    conv5_kernel<<<dim3(NP / 128, COUT / 128, BB), 256, SMEM_TOTAL>>>(x, bias, out);
    stats_kernel<<<1, 256>>>(gamma, beta);
    apply_kernel<<<(BB * COUT * NP / 4) / 256, 256>>>(out);
}

// round 7
// speedup vs baseline: 5.0946x; 1.1497x over previous
#include <cuda_runtime.h>
#include <cuda_fp16.h>
#include <cstdint>
#include <math.h>

#define BB    8
#define CIN   256
#define COUT  256
#define NP    8192
#define KT    9
#define DILT  6
#define PADT  24
#define NCHUNK 36          // (KT * CIN) / 64

// ---------------- device scratch ----------------
__device__ float   g_gw[BB * KT * NP];              // gate weights [b][k][n]
__device__ uint8_t g_A8[2 * NCHUNK * 16384];        // pre-swizzled fp16 W tiles
__device__ float   g_sum[COUT];
__device__ float   g_sumsq[COUT];
__device__ float   g_scale[COUT];
__device__ float   g_shift[COUT];

// ---------------- helpers ----------------
__device__ __forceinline__ uint32_t smem_u32(const void* p) {
    uint32_t a;
    asm("{ .reg .u64 t; cvta.to.shared.u64 t, %1; cvt.u32.u64 %0, t; }" : "=r"(a) : "l"(p));
    return a;
}
#define SW128(off) ((off) ^ (((off) >> 3) & 0x70))

__device__ __forceinline__ void cp16(uint32_t dst, const void* src) {
    asm volatile("cp.async.cg.shared.global [%0], [%1], 16;" :: "r"(dst), "l"(src));
}
__device__ __forceinline__ void cp8(uint32_t dst, const void* src) {
    asm volatile("cp.async.ca.shared.global [%0], [%1], 8;" :: "r"(dst), "l"(src));
}
__device__ __forceinline__ void sts_zero8(uint32_t dst) {
    asm volatile("st.shared.v2.f32 [%0], {%1, %1};" :: "r"(dst), "f"(0.f));
}
__device__ __forceinline__ void ldsm_x4(uint32_t* r, uint32_t addr) {
    asm volatile("ldmatrix.sync.aligned.m8n8.x4.shared.b16 {%0,%1,%2,%3}, [%4];"
        : "=r"(r[0]), "=r"(r[1]), "=r"(r[2]), "=r"(r[3]) : "r"(addr));
}
__device__ __forceinline__ void ldsm_x4t(uint32_t* r, uint32_t addr) {
    asm volatile("ldmatrix.sync.aligned.m8n8.x4.trans.shared.b16 {%0,%1,%2,%3}, [%4];"
        : "=r"(r[0]), "=r"(r[1]), "=r"(r[2]), "=r"(r[3]) : "r"(addr));
}
__device__ __forceinline__ void mma16816(float* c, const uint32_t* a, uint32_t b0, uint32_t b1) {
    asm volatile(
        "mma.sync.aligned.m16n8k16.row.col.f32.f16.f16.f32 "
        "{%0,%1,%2,%3}, {%4,%5,%6,%7}, {%8,%9}, {%0,%1,%2,%3};"
        : "+f"(c[0]), "+f"(c[1]), "+f"(c[2]), "+f"(c[3])
        : "r"(a[0]), "r"(a[1]), "r"(a[2]), "r"(a[3]), "r"(b0), "r"(b1));
}

// ---------------- kernel 0 ----------------
__global__ void zero_sums_kernel() {
    int t = threadIdx.x;
    g_sum[t] = 0.f;
    g_sumsq[t] = 0.f;
}

// ---------------- kernel 1: tap gate weights ----------------
__global__ void gweight_kernel(const float* __restrict__ coords,
                               const float* __restrict__ rot,
                               const float* __restrict__ dist) {
    int n = blockIdx.x * blockDim.x + threadIdx.x;
    int b = blockIdx.y;
    const float* cb = coords + (size_t)b * 3 * NP;
    const float* rb = rot    + (size_t)b * 3 * NP;

    float c0x = cb[n], c0y = cb[NP + n], c0z = cb[2 * NP + n];
    float r0x = rb[n], r0y = rb[NP + n], r0z = rb[2 * NP + n];
    float d0  = dist[(size_t)b * NP + n];
    float r0sq = r0x * r0x + r0y * r0y + r0z * r0z;

#pragma unroll
    for (int k = 0; k < KT; k++) {
        int j = n + k * DILT - PADT;
        float cjx = 0.f, cjy = 0.f, cjz = 0.f;
        float rjx = 0.f, rjy = 0.f, rjz = 0.f;
        float dj  = 0.f;
        if (j >= 0 && j < NP) {
            cjx = cb[j]; cjy = cb[NP + j]; cjz = cb[2 * NP + j];
            rjx = rb[j]; rjy = rb[NP + j]; rjz = rb[2 * NP + j];
            dj  = dist[(size_t)b * NP + j];
        }
        float dx = c0x - cjx, dy = c0y - cjy, dz = c0z - cjz;
        float dc = dx * dx + dy * dy + dz * dz;
        float dd = (d0 - dj) * (d0 - dj);
        float g  = expf(-0.5f * (dc + dd));
        float num  = r0x * rjx + r0y * rjy + r0z * rjz;
        float rjsq = rjx * rjx + rjy * rjy + rjz * rjz;
        float den  = sqrtf(r0sq * rjsq) + 1e-8f;
        g_gw[((size_t)b * KT + k) * NP + n] = g * fabsf(num / den);
    }
}

// ---------------- kernel 2: fp16 pre-swizzled W ----------------
__global__ void wsplit_kernel(const float* __restrict__ W) {
    int idx = blockIdx.x * 256 + threadIdx.x;
    if (idx >= 2 * NCHUNK * 128 * 64) return;
    int kc    = idx & 63;
    int t     = idx >> 6;
    int o_in  = t & 127;
    int t2    = t >> 7;
    int chunk = t2 % NCHUNK;
    int otile = t2 / NCHUNK;
    int k = chunk >> 2;
    int c = ((chunk & 3) << 6) + kc;
    int o = (otile << 7) + o_in;
    float val = W[((size_t)o * CIN + c) * KT + k];
    uint32_t sw = SW128((uint32_t)(o_in * 128 + kc * 2));
    size_t tb = (size_t)(otile * NCHUNK + chunk) * 16384;
    *(__half*)&g_A8[tb + sw] = __float2half(val);
}

// ---------------- SMEM layout ----------------
#define OFF_A   0          // 2 bufs x 16KB fp16 W        = 32768
#define OFF_X   32768      // 2 bufs x 32KB raw fp32 x    = 65536
#define OFF_B   98304      // 1 buf  x 16KB fp16 gated x  = 16384
#define OFF_ST  98304      // stats (overlays B, epilogue only)
#define SMEM_TOTAL 114688

// issue cp.async for raw x of chunk s into X[buf] (64 rows x 128 floats, 512B rows)
__device__ __forceinline__ void copyX(uint32_t sbase, int buf,
                                      const float* __restrict__ xb,
                                      int n_base, int s, int tid) {
    const int off = (s >> 2) * DILT - PADT;
    const int c0  = (s & 3) << 6;
    const uint32_t xd = sbase + OFF_X + buf * 32768;
#pragma unroll
    for (int q = 0; q < 16; q++) {
        int u   = tid + q * 256;       // 0..4095  (64 rows x 64 pairs)
        int row = u >> 6;
        int j   = (u & 63) << 1;       // pair of floats
        int src = n_base + off + j;
        uint32_t dst = xd + (uint32_t)(row * 512 + j * 4);
        if (src >= 0 && src < NP)      // pairs never straddle (offsets are 24B-multiples)
            cp8(dst, xb + (size_t)(c0 + row) * NP + src);
        else
            sts_zero8(dst);
    }
}

// convert X[buf] (fp32) -> gated fp16 swizzled B tile
__device__ __forceinline__ void convertB(char* smem, int xbuf, int b,
                                         int n_base, int s, int tid) {
    const int kk = s >> 2;
    const float4* gk4 = (const float4*)(g_gw + ((size_t)b * KT + kk) * NP + n_base);
    const char* xs = smem + OFF_X + xbuf * 32768;
#pragma unroll
    for (int it = 0; it < 8; it++) {
        int idx = tid + it * 256;
        int row = idx >> 5;            // kc row 0..63
        int j4  = idx & 31;
        int nn  = j4 << 2;
        float4 v  = *(const float4*)(xs + row * 512 + nn * 4);
        float4 g4 = gk4[j4];
        __half2 h01 = __floats2half2_rn(v.x * g4.x, v.y * g4.y);
        __half2 h23 = __floats2half2_rn(v.z * g4.z, v.w * g4.w);
        uint32_t ofs = (uint32_t)(row * 256) + (((uint32_t)(nn * 2)) ^ ((uint32_t)(row & 7) << 4));
        *(uint2*)(smem + OFF_B + ofs) = make_uint2(*(uint32_t*)&h01, *(uint32_t*)&h23);
    }
}

// ---------------- kernel 3: HMMA fused gated dilated conv ----------------
__global__ void __launch_bounds__(256, 2) conv6_kernel(
    const float* __restrict__ x,
    const float* __restrict__ bias,
    float* __restrict__ out) {

    extern __shared__ __align__(16) char smem[];
    const uint32_t sbase = smem_u32(smem);

    const int tid  = threadIdx.x;
    const int lane = tid & 31;
    const int wid  = tid >> 5;
    const int wm = wid & 3;
    const int wn = wid >> 2;
    const int g  = lane >> 2;
    const int tg = lane & 3;

    const int b      = blockIdx.z;
    const int n_base = blockIdx.x * 128;
    const int otile  = blockIdx.y;
    const int o_base = otile * 128;

    const float*   xb   = x + (size_t)b * CIN * NP;
    const uint8_t* Asrc = g_A8 + (size_t)otile * NCHUNK * 16384;

    const int a_row   = wm * 32 + ((lane >> 3) & 1) * 8 + (lane & 7);
    const int a_kb    = ((lane >> 4) & 1) * 16;
    const int b_nbyte = wn * 128 + ((lane >> 4) << 4);
    const int b_kcl   = lane & 15;

    float acc[2][8][4];
#pragma unroll
    for (int mt = 0; mt < 2; mt++)
#pragma unroll
        for (int nt = 0; nt < 8; nt++)
#pragma unroll
            for (int r = 0; r < 4; r++) acc[mt][nt][r] = 0.f;

    // ---- prologue: async-load chunk 0 (A + raw X) ----
    {
        const uint8_t* as = Asrc + tid * 16;
        const uint32_t ad = sbase + OFF_A + tid * 16;
#pragma unroll
        for (int q = 0; q < 4; q++) cp16(ad + q * 4096, as + q * 4096);
        copyX(sbase, 0, xb, n_base, 0, tid);
        asm volatile("cp.async.commit_group;");
    }

    // ---- mainloop ----
    for (int i = 0; i < NCHUNK; i++) {
        const int  cur = i & 1;
        const int  nxt = cur ^ 1;
        const bool hn  = (i + 1 < NCHUNK);

        asm volatile("cp.async.wait_group 0;" ::: "memory");
        __syncthreads();                         // X[cur]/A[cur] visible; B free

        if (hn) {                                // prefetch chunk i+1
            const uint8_t* as = Asrc + (size_t)(i + 1) * 16384 + tid * 16;
            const uint32_t ad = sbase + OFF_A + nxt * 16384 + tid * 16;
#pragma unroll
            for (int q = 0; q < 4; q++) cp16(ad + q * 4096, as + q * 4096);
            copyX(sbase, nxt, xb, n_base, i + 1, tid);
            asm volatile("cp.async.commit_group;");
        }

        convertB(smem, cur, b, n_base, i, tid);  // gate + fp16 into B
        __syncthreads();

        // compute chunk i
        {
            const uint32_t Ab = sbase + OFF_A + cur * 16384;
            const uint32_t Bb = sbase + OFF_B;
#pragma unroll
            for (int ks = 0; ks < 4; ks++) {
                uint32_t ah[2][4];
#pragma unroll
                for (int mt = 0; mt < 2; mt++) {
                    uint32_t byte = (uint32_t)((a_row + mt * 16) * 128 + ks * 32 + a_kb);
                    ldsm_x4(ah[mt], Ab + SW128(byte));
                }
                const int kc = ks * 16 + b_kcl;
                const uint32_t kb = (uint32_t)kc * 256;
                const uint32_t xm = ((uint32_t)kc & 7) << 4;
#pragma unroll
                for (int nt2 = 0; nt2 < 4; nt2++) {
                    uint32_t br[4];
                    const uint32_t nb = (uint32_t)(b_nbyte + nt2 * 32);
                    ldsm_x4t(br, Bb + kb + (nb ^ xm));
#pragma unroll
                    for (int mt = 0; mt < 2; mt++) {
                        mma16816(acc[mt][nt2 * 2 + 0], ah[mt], br[0], br[1]);
                        mma16816(acc[mt][nt2 * 2 + 1], ah[mt], br[2], br[3]);
                    }
                }
            }
        }
    }

    // ---- epilogue ----
    float* bst = (float*)(smem + OFF_ST);        // overlays B (done with it)
    __syncthreads();
    bst[tid] = 0.f;
    __syncthreads();

    float s4[4] = {0.f, 0.f, 0.f, 0.f}, q4[4] = {0.f, 0.f, 0.f, 0.f};
#pragma unroll
    for (int mt = 0; mt < 2; mt++) {
        const int r0v = wm * 32 + mt * 16 + g;
        const int r1v = r0v + 8;
        const float b0v = bias[o_base + r0v];
        const float b1v = bias[o_base + r1v];
        float* p0 = out + ((size_t)b * COUT + o_base + r0v) * NP + n_base + wn * 64 + 2 * tg;
        float* p1 = out + ((size_t)b * COUT + o_base + r1v) * NP + n_base + wn * 64 + 2 * tg;
#pragma unroll
        for (int nt = 0; nt < 8; nt++) {
            float v0 = acc[mt][nt][0] + b0v;
            float v1 = acc[mt][nt][1] + b0v;
            float v2 = acc[mt][nt][2] + b1v;
            float v3 = acc[mt][nt][3] + b1v;
            *(float2*)(p0 + nt * 8) = make_float2(v0, v1);
            *(float2*)(p1 + nt * 8) = make_float2(v2, v3);
            s4[mt * 2 + 0] += v0 + v1;  q4[mt * 2 + 0] += v0 * v0 + v1 * v1;
            s4[mt * 2 + 1] += v2 + v3;  q4[mt * 2 + 1] += v2 * v2 + v3 * v3;
        }
    }
#pragma unroll
    for (int r = 0; r < 4; r++) {
        float s = s4[r], q = q4[r];
        s += __shfl_xor_sync(0xffffffffu, s, 1);
        s += __shfl_xor_sync(0xffffffffu, s, 2);
        q += __shfl_xor_sync(0xffffffffu, q, 1);
        q += __shfl_xor_sync(0xffffffffu, q, 2);
        if (tg == 0) {
            int lr = wm * 32 + (r >> 1) * 16 + (r & 1) * 8 + g;
            atomicAdd(&bst[lr], s);
            atomicAdd(&bst[128 + lr], q);
        }
    }
    __syncthreads();
    if (tid < 128) {
        atomicAdd(&g_sum[o_base + tid],   bst[tid]);
        atomicAdd(&g_sumsq[o_base + tid], bst[128 + tid]);
    }
}

// ---------------- kernel 4: finalize BN stats ----------------
__global__ void stats_kernel(const float* __restrict__ gamma,
                             const float* __restrict__ beta) {
    int c = threadIdx.x;
    const float inv_n = 1.0f / (float)(BB * NP);
    float mean = g_sum[c] * inv_n;
    float var  = g_sumsq[c] * inv_n - mean * mean;
    float inv  = 1.0f / sqrtf(var + 1e-5f);
    float sc   = gamma[c] * inv;
    g_scale[c] = sc;
    g_shift[c] = beta[c] - mean * sc;
}

// ---------------- kernel 5: apply BN + ReLU ----------------
__global__ void apply_kernel(float* __restrict__ out) {
    size_t i4 = (size_t)blockIdx.x * blockDim.x + threadIdx.x;
    float4 v = ((float4*)out)[i4];
    int o = (int)((i4 * 4) >> 13) & (COUT - 1);
    float s = g_scale[o], t = g_shift[o];
    v.x = fmaxf(v.x * s + t, 0.f);
    v.y = fmaxf(v.y * s + t, 0.f);
    v.z = fmaxf(v.z * s + t, 0.f);
    v.w = fmaxf(v.w * s + t, 0.f);
    ((float4*)out)[i4] = v;
}

// ---------------- launch ----------------
extern "C" void kernel_launch(void* const* d_in, const int* in_sizes, int n_in,
                              void* d_out, int out_size) {
    const float* x      = (const float*)d_in[0];
    const float* coords = (const float*)d_in[1];
    const float* rot    = (const float*)d_in[2];
    const float* dist   = (const float*)d_in[3];
    const float* W      = (const float*)d_in[4];
    const float* bias   = (const float*)d_in[5];
    const float* gamma  = (const float*)d_in[6];
    const float* beta   = (const float*)d_in[7];
    float* out = (float*)d_out;

    cudaFuncSetAttribute(conv6_kernel, cudaFuncAttributeMaxDynamicSharedMemorySize, SMEM_TOTAL);

    zero_sums_kernel<<<1, 256>>>();
    gweight_kernel<<<dim3(NP / 256, BB), 256>>>(coords, rot, dist);
    wsplit_kernel<<<(2 * NCHUNK * 128 * 64 + 255) / 256, 256>>>(W);
    conv6_kernel<<<dim3(NP / 128, COUT / 128, BB), 256, SMEM_TOTAL>>>(x, bias, out);
    stats_kernel<<<1, 256>>>(gamma, beta);
    apply_kernel<<<(BB * COUT * NP / 4) / 256, 256>>>(out);
}

// round 10
// speedup vs baseline: 5.8340x; 1.1451x over previous
#include <cuda_runtime.h>
#include <cuda_fp16.h>
#include <cstdint>
#include <math.h>

#define BB    8
#define CIN   256
#define COUT  256
#define NP    8192
#define KT    9
#define DILT  6
#define PADT  24
#define NCHUNK 36          // (KT * CIN) / 64

// ---------------- device scratch ----------------
__device__ float   g_gw[BB * KT * NP];              // gate weights [b][k][n]
__device__ uint8_t g_A8[2 * NCHUNK * 16384];        // pre-swizzled fp16 W tiles
__device__ float   g_sum[COUT];
__device__ float   g_sumsq[COUT];
__device__ float   g_scale[COUT];
__device__ float   g_shift[COUT];

// ---------------- helpers ----------------
__device__ __forceinline__ uint32_t smem_u32(const void* p) {
    uint32_t a;
    asm("{ .reg .u64 t; cvta.to.shared.u64 t, %1; cvt.u32.u64 %0, t; }" : "=r"(a) : "l"(p));
    return a;
}
#define SW128(off) ((off) ^ (((off) >> 3) & 0x70))

__device__ __forceinline__ void cp16(uint32_t dst, const void* src) {
    asm volatile("cp.async.cg.shared.global [%0], [%1], 16;" :: "r"(dst), "l"(src));
}
__device__ __forceinline__ void cp8(uint32_t dst, const void* src) {
    asm volatile("cp.async.ca.shared.global [%0], [%1], 8;" :: "r"(dst), "l"(src));
}
__device__ __forceinline__ void cp4(uint32_t dst, const void* src) {
    asm volatile("cp.async.ca.shared.global [%0], [%1], 4;" :: "r"(dst), "l"(src));
}
__device__ __forceinline__ void sts_zero16(uint32_t dst) {
    asm volatile("st.shared.v4.f32 [%0], {%1, %1, %1, %1};" :: "r"(dst), "f"(0.f));
}
__device__ __forceinline__ void sts_zero4(uint32_t dst) {
    asm volatile("st.shared.f32 [%0], %1;" :: "r"(dst), "f"(0.f));
}
__device__ __forceinline__ void ldsm_x4(uint32_t* r, uint32_t addr) {
    asm volatile("ldmatrix.sync.aligned.m8n8.x4.shared.b16 {%0,%1,%2,%3}, [%4];"
        : "=r"(r[0]), "=r"(r[1]), "=r"(r[2]), "=r"(r[3]) : "r"(addr));
}
__device__ __forceinline__ void ldsm_x4t(uint32_t* r, uint32_t addr) {
    asm volatile("ldmatrix.sync.aligned.m8n8.x4.trans.shared.b16 {%0,%1,%2,%3}, [%4];"
        : "=r"(r[0]), "=r"(r[1]), "=r"(r[2]), "=r"(r[3]) : "r"(addr));
}
__device__ __forceinline__ void mma16816(float* c, const uint32_t* a, uint32_t b0, uint32_t b1) {
    asm volatile(
        "mma.sync.aligned.m16n8k16.row.col.f32.f16.f16.f32 "
        "{%0,%1,%2,%3}, {%4,%5,%6,%7}, {%8,%9}, {%0,%1,%2,%3};"
        : "+f"(c[0]), "+f"(c[1]), "+f"(c[2]), "+f"(c[3])
        : "r"(a[0]), "r"(a[1]), "r"(a[2]), "r"(a[3]), "r"(b0), "r"(b1));
}

// ---------------- kernel 0 ----------------
__global__ void zero_sums_kernel() {
    int t = threadIdx.x;
    g_sum[t] = 0.f;
    g_sumsq[t] = 0.f;
}

// ---------------- kernel 1: tap gate weights ----------------
__global__ void gweight_kernel(const float* __restrict__ coords,
                               const float* __restrict__ rot,
                               const float* __restrict__ dist) {
    int n = blockIdx.x * blockDim.x + threadIdx.x;
    int b = blockIdx.y;
    const float* cb = coords + (size_t)b * 3 * NP;
    const float* rb = rot    + (size_t)b * 3 * NP;

    float c0x = cb[n], c0y = cb[NP + n], c0z = cb[2 * NP + n];
    float r0x = rb[n], r0y = rb[NP + n], r0z = rb[2 * NP + n];
    float d0  = dist[(size_t)b * NP + n];
    float r0sq = r0x * r0x + r0y * r0y + r0z * r0z;

#pragma unroll
    for (int k = 0; k < KT; k++) {
        int j = n + k * DILT - PADT;
        float cjx = 0.f, cjy = 0.f, cjz = 0.f;
        float rjx = 0.f, rjy = 0.f, rjz = 0.f;
        float dj  = 0.f;
        if (j >= 0 && j < NP) {
            cjx = cb[j]; cjy = cb[NP + j]; cjz = cb[2 * NP + j];
            rjx = rb[j]; rjy = rb[NP + j]; rjz = rb[2 * NP + j];
            dj  = dist[(size_t)b * NP + j];
        }
        float dx = c0x - cjx, dy = c0y - cjy, dz = c0z - cjz;
        float dc = dx * dx + dy * dy + dz * dz;
        float dd = (d0 - dj) * (d0 - dj);
        float g  = expf(-0.5f * (dc + dd));
        float num  = r0x * rjx + r0y * rjy + r0z * rjz;
        float rjsq = rjx * rjx + rjy * rjy + rjz * rjz;
        float den  = sqrtf(r0sq * rjsq) + 1e-8f;
        g_gw[((size_t)b * KT + k) * NP + n] = g * fabsf(num / den);
    }
}

// ---------------- kernel 2: fp16 pre-swizzled W ----------------
__global__ void wsplit_kernel(const float* __restrict__ W) {
    int idx = blockIdx.x * 256 + threadIdx.x;
    if (idx >= 2 * NCHUNK * 128 * 64) return;
    int kc    = idx & 63;
    int t     = idx >> 6;
    int o_in  = t & 127;
    int t2    = t >> 7;
    int chunk = t2 % NCHUNK;
    int otile = t2 / NCHUNK;
    int k = chunk >> 2;
    int c = ((chunk & 3) << 6) + kc;
    int o = (otile << 7) + o_in;
    float val = W[((size_t)o * CIN + c) * KT + k];
    uint32_t sw = SW128((uint32_t)(o_in * 128 + kc * 2));
    size_t tb = (size_t)(otile * NCHUNK + chunk) * 16384;
    *(__half*)&g_A8[tb + sw] = __float2half(val);
}

// ---------------- SMEM layout ----------------
#define OFF_A   0          // 2 bufs x 16KB fp16 W          = 32768
#define OFF_X   32768      // 1 buf  x 32KB raw fp32 x      = 32768
#define OFF_B   65536      // 2 bufs x 16KB fp16 gated x    = 32768
#define OFF_ST  98304      // stats: 256 floats
#define SMEM_TOTAL 99328

// Self-mapped X staging: thread tid owns cols [nn, nn+4) (floats), rows (tid>>5)+8*it.
// copyX writes ONLY these bytes; convertB reads ONLY these bytes -> no cross-thread
// hazard on X: one X buffer, no barrier between wait_group and convert.
// NOTE: tap offsets are multiples of 6 floats (24B): global addr is 16B-aligned only
// when (off & 3) == 0 (even taps); odd taps use 8B copies (24B => 8B-aligned).

__device__ __forceinline__ void copyX(uint32_t sbase,
                                      const float* __restrict__ xb,
                                      int n_base, int s, int tid) {
    const int off = (s >> 2) * DILT - PADT;
    const int c0  = (s & 3) << 6;
    const int nn  = (tid & 31) << 2;             // float col
    const int r0  = tid >> 5;                    // base row
    const int src = n_base + off + nn;
    const uint32_t xd = sbase + OFF_X + (uint32_t)(r0 * 512 + nn * 4);
    const float* gs = xb + (size_t)(c0 + r0) * NP + src;

    if (src >= 0 && src + 3 < NP) {              // interior
        if ((off & 3) == 0) {                    // 16B-aligned tap
#pragma unroll
            for (int it = 0; it < 8; it++)
                cp16(xd + it * 4096, gs + (size_t)it * 8 * NP);
        } else {                                 // 8B-aligned tap
#pragma unroll
            for (int it = 0; it < 8; it++) {
                const float* gp = gs + (size_t)it * 8 * NP;
                cp8(xd + it * 4096,     gp);
                cp8(xd + it * 4096 + 8, gp + 2);
            }
        }
    } else if (src + 3 < 0 || src >= NP) {       // fully out of range
#pragma unroll
        for (int it = 0; it < 8; it++)
            sts_zero16(xd + it * 4096);
    } else {                                     // straddle (rare, edge CTAs)
#pragma unroll
        for (int it = 0; it < 8; it++)
#pragma unroll
            for (int e = 0; e < 4; e++) {
                if (src + e >= 0 && src + e < NP)
                    cp4(xd + it * 4096 + e * 4, gs + (size_t)it * 8 * NP + e);
                else
                    sts_zero4(xd + it * 4096 + e * 4);
            }
    }
}

// convert own X bytes -> gated fp16 swizzled B tile
__device__ __forceinline__ void convertB(char* smem, uint32_t bofs, int b,
                                         int n_base, int s, int tid) {
    const int kk = s >> 2;
    const int nn = (tid & 31) << 2;
    const int r0 = tid >> 5;
    const float4 g4 = *(const float4*)(g_gw + ((size_t)b * KT + kk) * NP + n_base + nn);
    const char* xs = smem + OFF_X + r0 * 512 + nn * 4;
#pragma unroll
    for (int it = 0; it < 8; it++) {
        int row = r0 + it * 8;
        float4 v = *(const float4*)(xs + it * 4096);
        __half2 h01 = __floats2half2_rn(v.x * g4.x, v.y * g4.y);
        __half2 h23 = __floats2half2_rn(v.z * g4.z, v.w * g4.w);
        uint32_t ofs = (uint32_t)(row * 256) + (((uint32_t)(nn * 2)) ^ ((uint32_t)(row & 7) << 4));
        *(uint2*)(smem + bofs + ofs) = make_uint2(*(uint32_t*)&h01, *(uint32_t*)&h23);
    }
}

// ---------------- kernel 3: HMMA fused gated dilated conv ----------------
__global__ void __launch_bounds__(256, 2) conv8_kernel(
    const float* __restrict__ x,
    const float* __restrict__ bias,
    float* __restrict__ out) {

    extern __shared__ __align__(16) char smem[];
    const uint32_t sbase = smem_u32(smem);

    const int tid  = threadIdx.x;
    const int lane = tid & 31;
    const int wid  = tid >> 5;
    const int wm = wid & 3;
    const int wn = wid >> 2;
    const int g  = lane >> 2;
    const int tg = lane & 3;

    const int b      = blockIdx.z;
    const int n_base = blockIdx.x * 128;
    const int otile  = blockIdx.y;
    const int o_base = otile * 128;

    const float*   xb   = x + (size_t)b * CIN * NP;
    const uint8_t* Asrc = g_A8 + (size_t)otile * NCHUNK * 16384;

    const int a_row   = wm * 32 + ((lane >> 3) & 1) * 8 + (lane & 7);
    const int a_kb    = ((lane >> 4) & 1) * 16;
    const int b_nbyte = wn * 128 + ((lane >> 4) << 4);
    const int b_kcl   = lane & 15;

    float acc[2][8][4];
#pragma unroll
    for (int mt = 0; mt < 2; mt++)
#pragma unroll
        for (int nt = 0; nt < 8; nt++)
#pragma unroll
            for (int r = 0; r < 4; r++) acc[mt][nt][r] = 0.f;

    // ---- prologue ----
    {
        // G0: A[0] -> Abuf0, X[0]
        const uint8_t* as = Asrc + tid * 16;
#pragma unroll
        for (int q = 0; q < 4; q++) cp16(sbase + OFF_A + tid * 16 + q * 4096, as + q * 4096);
        copyX(sbase, xb, n_base, 0, tid);
        asm volatile("cp.async.commit_group;");
        // drain G0, convert chunk 0 (own-thread X, no barrier needed)
        asm volatile("cp.async.wait_group 0;" ::: "memory");
        convertB(smem, OFF_B, b, n_base, 0, tid);
        __syncthreads();                          // B[0] + A[0] visible to all
        // G1: A[1] -> Abuf1, X[1]
        const uint8_t* as1 = Asrc + 16384 + tid * 16;
#pragma unroll
        for (int q = 0; q < 4; q++) cp16(sbase + OFF_A + 16384 + tid * 16 + q * 4096, as1 + q * 4096);
        copyX(sbase, xb, n_base, 1, tid);
        asm volatile("cp.async.commit_group;");
    }

    // ---- mainloop: ONE sync per chunk ----
    for (int i = 0; i < NCHUNK; i++) {
        const int cur = i & 1;

        // compute chunk i from A[cur], B[cur]
        {
            const uint32_t Ab = sbase + OFF_A + cur * 16384;
            const uint32_t Bb = sbase + OFF_B + cur * 16384;
#pragma unroll
            for (int ks = 0; ks < 4; ks++) {
                uint32_t ah[2][4];
#pragma unroll
                for (int mt = 0; mt < 2; mt++) {
                    uint32_t byte = (uint32_t)((a_row + mt * 16) * 128 + ks * 32 + a_kb);
                    ldsm_x4(ah[mt], Ab + SW128(byte));
                }
                const int kc = ks * 16 + b_kcl;
                const uint32_t kb = (uint32_t)kc * 256;
                const uint32_t xm = ((uint32_t)kc & 7) << 4;
#pragma unroll
                for (int nt2 = 0; nt2 < 4; nt2++) {
                    uint32_t br[4];
                    const uint32_t nb = (uint32_t)(b_nbyte + nt2 * 32);
                    ldsm_x4t(br, Bb + kb + (nb ^ xm));
#pragma unroll
                    for (int mt = 0; mt < 2; mt++) {
                        mma16816(acc[mt][nt2 * 2 + 0], ah[mt], br[0], br[1]);
                        mma16816(acc[mt][nt2 * 2 + 1], ah[mt], br[2], br[3]);
                    }
                }
            }
        }

        if (i + 1 < NCHUNK) {
            // X[i+1]/A[i+1] landed (committed one chunk ago)
            asm volatile("cp.async.wait_group 0;" ::: "memory");
            // convert own X bytes -> B[nxt]; no barrier needed before this
            convertB(smem, OFF_B + (cur ^ 1) * 16384, b, n_base, i + 1, tid);
        }
        __syncthreads();   // B[nxt] ready; A[cur] readers done -> safe to overwrite
        if (i + 2 < NCHUNK) {
            const uint8_t* as = Asrc + (size_t)(i + 2) * 16384 + tid * 16;
            const uint32_t ad = sbase + OFF_A + cur * 16384 + tid * 16;
#pragma unroll
            for (int q = 0; q < 4; q++) cp16(ad + q * 4096, as + q * 4096);
            copyX(sbase, xb, n_base, i + 2, tid);
            asm volatile("cp.async.commit_group;");
        }
    }

    // ---- epilogue ----
    float* bst = (float*)(smem + OFF_ST);
    bst[tid] = 0.f;
    __syncthreads();

    float s4[4] = {0.f, 0.f, 0.f, 0.f}, q4[4] = {0.f, 0.f, 0.f, 0.f};
#pragma unroll
    for (int mt = 0; mt < 2; mt++) {
        const int r0v = wm * 32 + mt * 16 + g;
        const int r1v = r0v + 8;
        const float b0v = bias[o_base + r0v];
        const float b1v = bias[o_base + r1v];
        float* p0 = out + ((size_t)b * COUT + o_base + r0v) * NP + n_base + wn * 64 + 2 * tg;
        float* p1 = out + ((size_t)b * COUT + o_base + r1v) * NP + n_base + wn * 64 + 2 * tg;
#pragma unroll
        for (int nt = 0; nt < 8; nt++) {
            float v0 = acc[mt][nt][0] + b0v;
            float v1 = acc[mt][nt][1] + b0v;
            float v2 = acc[mt][nt][2] + b1v;
            float v3 = acc[mt][nt][3] + b1v;
            *(float2*)(p0 + nt * 8) = make_float2(v0, v1);
            *(float2*)(p1 + nt * 8) = make_float2(v2, v3);
            s4[mt * 2 + 0] += v0 + v1;  q4[mt * 2 + 0] += v0 * v0 + v1 * v1;
            s4[mt * 2 + 1] += v2 + v3;  q4[mt * 2 + 1] += v2 * v2 + v3 * v3;
        }
    }
#pragma unroll
    for (int r = 0; r < 4; r++) {
        float s = s4[r], q = q4[r];
        s += __shfl_xor_sync(0xffffffffu, s, 1);
        s += __shfl_xor_sync(0xffffffffu, s, 2);
        q += __shfl_xor_sync(0xffffffffu, q, 1);
        q += __shfl_xor_sync(0xffffffffu, q, 2);
        if (tg == 0) {
            int lr = wm * 32 + (r >> 1) * 16 + (r & 1) * 8 + g;
            atomicAdd(&bst[lr], s);
            atomicAdd(&bst[128 + lr], q);
        }
    }
    __syncthreads();
    if (tid < 128) {
        atomicAdd(&g_sum[o_base + tid],   bst[tid]);
        atomicAdd(&g_sumsq[o_base + tid], bst[128 + tid]);
    }
}

// ---------------- kernel 4: finalize BN stats ----------------
__global__ void stats_kernel(const float* __restrict__ gamma,
                             const float* __restrict__ beta) {
    int c = threadIdx.x;
    const float inv_n = 1.0f / (float)(BB * NP);
    float mean = g_sum[c] * inv_n;
    float var  = g_sumsq[c] * inv_n - mean * mean;
    float inv  = 1.0f / sqrtf(var + 1e-5f);
    float sc   = gamma[c] * inv;
    g_scale[c] = sc;
    g_shift[c] = beta[c] - mean * sc;
}

// ---------------- kernel 5: apply BN + ReLU ----------------
__global__ void apply_kernel(float* __restrict__ out) {
    size_t i4 = (size_t)blockIdx.x * blockDim.x + threadIdx.x;
    float4 v = ((float4*)out)[i4];
    int o = (int)((i4 * 4) >> 13) & (COUT - 1);
    float s = g_scale[o], t = g_shift[o];
    v.x = fmaxf(v.x * s + t, 0.f);
    v.y = fmaxf(v.y * s + t, 0.f);
    v.z = fmaxf(v.z * s + t, 0.f);
    v.w = fmaxf(v.w * s + t, 0.f);
    ((float4*)out)[i4] = v;
}

// ---------------- launch ----------------
extern "C" void kernel_launch(void* const* d_in, const int* in_sizes, int n_in,
                              void* d_out, int out_size) {
    const float* x      = (const float*)d_in[0];
    const float* coords = (const float*)d_in[1];
    const float* rot    = (const float*)d_in[2];
    const float* dist   = (const float*)d_in[3];
    const float* W      = (const float*)d_in[4];
    const float* bias   = (const float*)d_in[5];
    const float* gamma  = (const float*)d_in[6];
    const float* beta   = (const float*)d_in[7];
    float* out = (float*)d_out;

    cudaFuncSetAttribute(conv8_kernel, cudaFuncAttributeMaxDynamicSharedMemorySize, SMEM_TOTAL);

    zero_sums_kernel<<<1, 256>>>();
    gweight_kernel<<<dim3(NP / 256, BB), 256>>>(coords, rot, dist);
    wsplit_kernel<<<(2 * NCHUNK * 128 * 64 + 255) / 256, 256>>>(W);
    conv8_kernel<<<dim3(NP / 128, COUT / 128, BB), 256, SMEM_TOTAL>>>(x, bias, out);
    stats_kernel<<<1, 256>>>(gamma, beta);
    apply_kernel<<<(BB * COUT * NP / 4) / 256, 256>>>(out);
}